// round 3
// baseline (speedup 1.0000x reference)
#include <cuda_runtime.h>
#include <cuda_bf16.h>

// MultitaskReadout: y[b,t,:] = concat of per-decoder Linear outputs, masked by
// decoder_index[b,t]. x[16,4096,1024] f32, dims {2,2,30}, out [16,4096,34] f32.
//
//   K1 (k_compact): bucket token indices into 3 per-decoder lists.
//   K2 (k_readout): warp-PAIR handles 4 same-decoder tokens; each warp owns
//       half the 1024-dim (64 x-regs/lane), W rows streamed via __ldg (L1-hot),
//       packed fma.rn.f32x2, per-row butterfly + cross-warp smem combine,
//       full 136B output row written per token (fused zeroing; no k_zero pass).
//       Last block resets compaction counters (post-state == pre-state).

#define NTOK   65536      // B*T
#define DIM    1024
#define HDIM   512        // per-warp half
#define G      4          // tokens per warp-pair
#define OUTC   34         // 2 + 2 + 30

typedef unsigned long long u64;

__device__ int g_list[3 * NTOK];
__device__ int g_cnt[3];
__device__ int g_done;

// ---- packed f32x2 helpers --------------------------------------------------
__device__ __forceinline__ void fma2(u64& acc, u64 a, u64 b) {
    asm("fma.rn.f32x2 %0, %1, %2, %0;" : "+l"(acc) : "l"(a), "l"(b));
}
__device__ __forceinline__ float pair_sum(u64 v) {
    float lo, hi;
    asm("mov.b64 {%0,%1}, %2;" : "=f"(lo), "=f"(hi) : "l"(v));
    return lo + hi;
}

// ---------------------------------------------------------------------------
__global__ void k_compact(const int* __restrict__ didx) {
    __shared__ int s_cnt[3];
    __shared__ int s_base[3];
    int t = threadIdx.x;
    if (t < 3) s_cnt[t] = 0;
    __syncthreads();

    int i = blockIdx.x * blockDim.x + t;   // grid sized exactly NTOK/256
    int d = didx[i];
    int lp = atomicAdd(&s_cnt[d], 1);
    __syncthreads();

    if (t < 3) s_base[t] = atomicAdd(&g_cnt[t], s_cnt[t]);
    __syncthreads();

    g_list[d * NTOK + s_base[d] + lp] = i;
}

// ---------------------------------------------------------------------------
// 128 threads = 4 warps = 2 warp-pairs per block.
__global__ void __launch_bounds__(128)
k_readout(const float* __restrict__ x,
          const float* __restrict__ W0, const float* __restrict__ b0,
          const float* __restrict__ W1, const float* __restrict__ b1,
          const float* __restrict__ W2, const float* __restrict__ b2,
          float* __restrict__ out) {
    __shared__ float4 s_part[2][2];            // [pairLocal][row parity]
    __shared__ float  s_out[2][G][OUTC];       // staged full output rows

    const int tid   = threadIdx.x;
    const int lane  = tid & 31;
    const int wid   = tid >> 5;                // 0..3
    const int h     = wid & 1;                 // half of dim
    const int plocal = wid >> 1;               // pair within block (0,1)
    const int pid   = blockIdx.x * 2 + plocal; // global pair id
    const int ptid  = tid & 63;                // thread id within pair
    const int barid = 1 + plocal;              // named barrier per pair

    const int c0 = g_cnt[0], c1 = g_cnt[1], c2 = g_cnt[2];
    const int ng0 = (c0 + G - 1) / G;
    const int ng1 = (c1 + G - 1) / G;
    const int ng2 = (c2 + G - 1) / G;

    int d = -1, slot = 0, n = 0;
    if (pid < ng0)                  { d = 0; slot = pid;             n = c0; }
    else if (pid < ng0 + ng1)       { d = 1; slot = pid - ng0;       n = c1; }
    else if (pid < ng0 + ng1 + ng2) { d = 2; slot = pid - ng0 - ng1; n = c2; }

    if (d >= 0) {
        const int* list = g_list + d * NTOK;
        const int  base = slot * G;
        const int  nvalid = min(G, n - base);

        int tok[G];
#pragma unroll
        for (int t = 0; t < G; t++) tok[t] = list[base + min(t, nvalid - 1)];

        // zero the staged output rows for this pair (64 threads, 136 floats)
        {
            float* so = &s_out[plocal][0][0];
            for (int i = ptid; i < G * OUTC; i += 64) so[i] = 0.f;
        }

        // load x halves: lane covers elems h*512 + 4*lane + 128*j (+0..3), j=0..3
        // packed as f32x2 pairs (16 floats = 8 u64 per token per lane)
        u64 xr[G][4][2];
#pragma unroll
        for (int t = 0; t < G; t++) {
            const ulonglong2* xp = reinterpret_cast<const ulonglong2*>(
                x + (size_t)tok[t] * DIM + h * HDIM + lane * 4);
#pragma unroll
            for (int j = 0; j < 4; j++) {
                ulonglong2 v = xp[j * 32];     // stride 128 floats
                xr[t][j][0] = v.x; xr[t][j][1] = v.y;
            }
        }

        const float* W; const float* bb; int rows, off;
        if (d == 0)      { W = W0; bb = b0; rows = 2;  off = 0; }
        else if (d == 1) { W = W1; bb = b1; rows = 2;  off = 2; }
        else             { W = W2; bb = b2; rows = 30; off = 4; }

        asm volatile("bar.sync %0, 64;" :: "r"(barid) : "memory");  // s_out zeroed

        for (int r = 0; r < rows; r++) {
            const ulonglong2* wp = reinterpret_cast<const ulonglong2*>(
                W + (size_t)r * DIM + h * HDIM + lane * 4);
            u64 acc0 = 0ull, acc1 = 0ull, acc2 = 0ull, acc3 = 0ull;
#pragma unroll
            for (int j = 0; j < 4; j++) {
                ulonglong2 w = __ldg(wp + j * 32);
                fma2(acc0, w.x, xr[0][j][0]); fma2(acc0, w.y, xr[0][j][1]);
                fma2(acc1, w.x, xr[1][j][0]); fma2(acc1, w.y, xr[1][j][1]);
                fma2(acc2, w.x, xr[2][j][0]); fma2(acc2, w.y, xr[2][j][1]);
                fma2(acc3, w.x, xr[3][j][0]); fma2(acc3, w.y, xr[3][j][1]);
            }
            float s0 = pair_sum(acc0), s1 = pair_sum(acc1);
            float s2 = pair_sum(acc2), s3 = pair_sum(acc3);
#pragma unroll
            for (int s = 16; s > 0; s >>= 1) {
                s0 += __shfl_down_sync(0xFFFFFFFFu, s0, s);
                s1 += __shfl_down_sync(0xFFFFFFFFu, s1, s);
                s2 += __shfl_down_sync(0xFFFFFFFFu, s2, s);
                s3 += __shfl_down_sync(0xFFFFFFFFu, s3, s);
            }
            if (h == 1 && lane == 0)
                s_part[plocal][r & 1] = make_float4(s0, s1, s2, s3);
            asm volatile("bar.sync %0, 64;" :: "r"(barid) : "memory");
            if (h == 0 && lane == 0) {
                float4 o = s_part[plocal][r & 1];
                float bv = __ldg(bb + r);
                s_out[plocal][0][off + r] = s0 + o.x + bv;
                s_out[plocal][1][off + r] = s1 + o.y + bv;
                s_out[plocal][2][off + r] = s2 + o.z + bv;
                s_out[plocal][3][off + r] = s3 + o.w + bv;
            }
        }

        asm volatile("bar.sync %0, 64;" :: "r"(barid) : "memory");  // s_out ready

        // cooperative full-row write: nvalid tokens x 34 floats each
        const float* so = &s_out[plocal][0][0];
        for (int i = ptid; i < nvalid * OUTC; i += 64) {
            int t  = i / OUTC;
            int ch = i - t * OUTC;
            out[(size_t)tok[t] * OUTC + ch] = so[i];
        }
    }

    // counter reset by the last block to finish (post-state == pre-state)
    __syncthreads();
    if (tid == 0) {
        int done = atomicAdd(&g_done, 1);
        if (done == gridDim.x - 1) {
            g_cnt[0] = 0; g_cnt[1] = 0; g_cnt[2] = 0;
            g_done = 0;
        }
    }
}

// ---------------------------------------------------------------------------
extern "C" void kernel_launch(void* const* d_in, const int* in_sizes, int n_in,
                              void* d_out, int out_size) {
    const float* x    = (const float*)d_in[0];
    const int*   didx = (const int*)  d_in[1];
    const float* W0   = (const float*)d_in[2];
    const float* b0   = (const float*)d_in[3];
    const float* W1   = (const float*)d_in[4];
    const float* b1   = (const float*)d_in[5];
    const float* W2   = (const float*)d_in[6];
    const float* b2   = (const float*)d_in[7];
    float* out = (float*)d_out;

    // K1: compaction (exactly NTOK threads); counters start at 0
    // (static init on first call, last k_readout block resets thereafter)
    k_compact<<<NTOK / 256, 256>>>(didx);

    // K2: readout. Worst-case pairs = ceil(NTOK/G)+2 = 16386 -> 8193 blocks
    const int max_pairs = (NTOK + G - 1) / G + 2;
    const int nblocks = (max_pairs + 1) / 2;
    k_readout<<<nblocks, 128>>>(x, W0, b0, W1, b1, W2, b2, out);
}